// round 16
// baseline (speedup 1.0000x reference)
#include <cuda_runtime.h>
#include <cuda_fp16.h>
#include <cstddef>
#include <cstdint>

// Problem constants
#define BB 2
#define SS 2048
#define DD 2048
#define NH 16
#define FHD 128
#define KDIM 2048
#define NDIM 2048
#define MDIM (BB * SS)   // 4096

// ---------------------------------------------------------------------------
// Scratch (device globals — no allocation allowed)
// ---------------------------------------------------------------------------
__device__ __half g_Qh[(size_t)MDIM * DD];
__device__ __half g_Kh[(size_t)MDIM * DD];
__device__ __half g_Vh[(size_t)MDIM * DD];
__device__ __half g_AOh[(size_t)MDIM * DD];
__device__ __half g_xh[(size_t)MDIM * KDIM];
__device__ __half g_wqh[(size_t)NDIM * KDIM];
__device__ __half g_wkh[(size_t)NDIM * KDIM];
__device__ __half g_wvh[(size_t)NDIM * KDIM];
__device__ __half g_woh[(size_t)NDIM * KDIM];

// ---------------------------------------------------------------------------
// Helpers
// ---------------------------------------------------------------------------
__device__ __forceinline__ uint32_t smem_u32(const void* p) {
    uint32_t a;
    asm("{ .reg .u64 t; cvta.to.shared.u64 t, %1; cvt.u32.u64 %0, t; }" : "=r"(a) : "l"(p));
    return a;
}
__device__ __forceinline__ void cp_async16(uint32_t dst, const void* src) {
    asm volatile("cp.async.cg.shared.global [%0], [%1], 16;" :: "r"(dst), "l"(src) : "memory");
}
__device__ __forceinline__ void cp_commit() {
    asm volatile("cp.async.commit_group;" ::: "memory");
}
template <int N>
__device__ __forceinline__ void cp_wait() {
    asm volatile("cp.async.wait_group %0;" :: "n"(N) : "memory");
}
__device__ __forceinline__ void ldsm4(uint32_t& r0, uint32_t& r1, uint32_t& r2, uint32_t& r3,
                                      uint32_t addr) {
    asm volatile("ldmatrix.sync.aligned.m8n8.x4.shared.b16 {%0,%1,%2,%3}, [%4];"
                 : "=r"(r0), "=r"(r1), "=r"(r2), "=r"(r3) : "r"(addr));
}
__device__ __forceinline__ void ldsm4t(uint32_t& r0, uint32_t& r1, uint32_t& r2, uint32_t& r3,
                                       uint32_t addr) {
    asm volatile("ldmatrix.sync.aligned.m8n8.x4.trans.shared.b16 {%0,%1,%2,%3}, [%4];"
                 : "=r"(r0), "=r"(r1), "=r"(r2), "=r"(r3) : "r"(addr));
}
__device__ __forceinline__ void mma_f16(float* d, const uint32_t* a, uint32_t b0, uint32_t b1)
{
    asm volatile(
        "mma.sync.aligned.m16n8k16.row.col.f32.f16.f16.f32 "
        "{%0,%1,%2,%3}, {%4,%5,%6,%7}, {%8,%9}, {%0,%1,%2,%3};"
        : "+f"(d[0]), "+f"(d[1]), "+f"(d[2]), "+f"(d[3])
        : "r"(a[0]), "r"(a[1]), "r"(a[2]), "r"(a[3]), "r"(b0), "r"(b1));
}

// ---------------------------------------------------------------------------
// fp16 mma GEMM mainloop: 128-thread CTA, 4 warps of 64x64, 2 CTAs/SM,
// K-tile 32, 5-stage ring (one extra tile of producer slack vs R14),
// one barrier per k-tile, double-buffered ldmatrix fragments.
// ---------------------------------------------------------------------------
#define GTM 128
#define GTN 128
#define GTK 32
#define GSTR 80
#define NTHR 128
#define A_T_B (GTM * GSTR)                 // 10240
#define B_T_B (GTN * GSTR)                 // 10240
#define STG_B (A_T_B + B_T_B)              // 20480
#define NSTG 5
#define GEMM_SMEM (NSTG * STG_B)           // 102400 (x2 CTAs = 204.8 KB/SM)
#define KT (KDIM / GTK)                    // 64

__device__ __forceinline__ void gemm_load_stage(uint32_t sbase, int s, int kt,
                                                const __half* __restrict__ A,
                                                const __half* __restrict__ Bm,
                                                int m0, int n0, int tid)
{
    const uint32_t ab = sbase + s * STG_B;
    const uint32_t bb = ab + A_T_B;
    const int kk = kt * GTK;
#pragma unroll
    for (int i = 0; i < 4; i++) {
        int t = tid + i * NTHR;
        int r = t >> 2, c = t & 3;
        cp_async16(ab + r * GSTR + c * 16, A + (size_t)(m0 + r) * KDIM + kk + c * 8);
    }
#pragma unroll
    for (int i = 0; i < 4; i++) {
        int t = tid + i * NTHR;
        int r = t >> 2, c = t & 3;
        cp_async16(bb + r * GSTR + c * 16, Bm + (size_t)(n0 + r) * KDIM + kk + c * 8);
    }
}

__device__ __forceinline__ void gemm_mainloop(const __half* __restrict__ A,
                                              const __half* __restrict__ Bm,
                                              int m0, int n0,
                                              float acc[4][8][4])
{
    extern __shared__ __align__(16) char smem[];
    const uint32_t sbase = smem_u32(smem);
    const int tid = threadIdx.x;
    const int wid = tid >> 5, lane = tid & 31;
    const int wm = (wid >> 1) * 64, wn = (wid & 1) * 64;
    const int l15 = lane & 15, lhi = (lane >> 4) * 16;
    const uint32_t aoff = (wm + l15) * GSTR + lhi;
    const uint32_t boff = (wn + l15) * GSTR + lhi;

#pragma unroll
    for (int mi = 0; mi < 4; mi++)
#pragma unroll
        for (int ni = 0; ni < 8; ni++)
#pragma unroll
            for (int j = 0; j < 4; j++) acc[mi][ni][j] = 0.0f;

#pragma unroll
    for (int s = 0; s < NSTG - 1; s++) {
        gemm_load_stage(sbase, s, s, A, Bm, m0, n0, tid);
        cp_commit();
    }
    cp_wait<2>();
    __syncthreads();

    uint32_t a0[4][4], b0f[4][4];
    uint32_t a1[4][4], b1f[4][4];
    {
        const uint32_t ab = sbase;
        const uint32_t bb = ab + A_T_B;
#pragma unroll
        for (int mi = 0; mi < 4; mi++)
            ldsm4(a0[mi][0], a0[mi][1], a0[mi][2], a0[mi][3],
                  ab + aoff + mi * 16 * GSTR);
#pragma unroll
        for (int nj = 0; nj < 4; nj++)
            ldsm4(b0f[nj][0], b0f[nj][1], b0f[nj][2], b0f[nj][3],
                  bb + boff + nj * 16 * GSTR);
    }

    int st_cur = 0, st_wr = NSTG - 1;
    for (int kt = 0; kt < KT; kt++) {
        cp_wait<2>();
        __syncthreads();
        if (kt + NSTG - 1 < KT)
            gemm_load_stage(sbase, st_wr, kt + NSTG - 1, A, Bm, m0, n0, tid);
        cp_commit();

        const uint32_t ab = sbase + st_cur * STG_B;
        const uint32_t bb = ab + A_T_B;
        const int st_nxt = (st_cur + 1 == NSTG) ? 0 : st_cur + 1;

#pragma unroll
        for (int mi = 0; mi < 4; mi++)
            ldsm4(a1[mi][0], a1[mi][1], a1[mi][2], a1[mi][3],
                  ab + aoff + mi * 16 * GSTR + 32);
#pragma unroll
        for (int nj = 0; nj < 4; nj++)
            ldsm4(b1f[nj][0], b1f[nj][1], b1f[nj][2], b1f[nj][3],
                  bb + boff + nj * 16 * GSTR + 32);

#pragma unroll
        for (int nj = 0; nj < 4; nj++)
#pragma unroll
            for (int mi = 0; mi < 4; mi++) {
                mma_f16(acc[mi][2 * nj],     a0[mi], b0f[nj][0], b0f[nj][2]);
                mma_f16(acc[mi][2 * nj + 1], a0[mi], b0f[nj][1], b0f[nj][3]);
            }

        if (kt + 1 < KT) {
            const uint32_t abn = sbase + st_nxt * STG_B;
            const uint32_t bbn = abn + A_T_B;
#pragma unroll
            for (int mi = 0; mi < 4; mi++)
                ldsm4(a0[mi][0], a0[mi][1], a0[mi][2], a0[mi][3],
                      abn + aoff + mi * 16 * GSTR);
#pragma unroll
            for (int nj = 0; nj < 4; nj++)
                ldsm4(b0f[nj][0], b0f[nj][1], b0f[nj][2], b0f[nj][3],
                      bbn + boff + nj * 16 * GSTR);
        }

#pragma unroll
        for (int nj = 0; nj < 4; nj++)
#pragma unroll
            for (int mi = 0; mi < 4; mi++) {
                mma_f16(acc[mi][2 * nj],     a1[mi], b1f[nj][0], b1f[nj][2]);
                mma_f16(acc[mi][2 * nj + 1], a1[mi], b1f[nj][1], b1f[nj][3]);
            }

        st_cur = st_nxt;
        st_wr = (st_wr + 1 == NSTG) ? 0 : st_wr + 1;
    }
}

__global__ void __launch_bounds__(NTHR, 2) gemm_f16_kernel(
    const __half* __restrict__ A, const __half* __restrict__ Bm, float* __restrict__ C)
{
    const int tid = threadIdx.x;
    const int wid = tid >> 5, lane = tid & 31;
    const int g = lane >> 2, q = lane & 3;
    const int m0 = blockIdx.y * GTM, n0 = blockIdx.x * GTN;
    const int wm = (wid >> 1) * 64, wn = (wid & 1) * 64;

    float acc[4][8][4];
    gemm_mainloop(A, Bm, m0, n0, acc);

#pragma unroll
    for (int mi = 0; mi < 4; mi++) {
        int row = m0 + wm + mi * 16 + g;
#pragma unroll
        for (int ni = 0; ni < 8; ni++) {
            int col = n0 + wn + ni * 8 + q * 2;
            *(float2*)(C + (size_t)row * NDIM + col) =
                make_float2(acc[mi][ni][0], acc[mi][ni][1]);
            *(float2*)(C + (size_t)(row + 8) * NDIM + col) =
                make_float2(acc[mi][ni][2], acc[mi][ni][3]);
        }
    }
}

__global__ void __launch_bounds__(NTHR, 2) qkv_f16_kernel(
    const __half* __restrict__ A,
    const float* __restrict__ fc, const float* __restrict__ fs)
{
    const __half* Bm;
    __half* C;
    const int z = blockIdx.z;
    if (z == 0)      { Bm = g_wqh; C = g_Qh; }
    else if (z == 1) { Bm = g_wkh; C = g_Kh; }
    else             { Bm = g_wvh; C = g_Vh; }

    const int tid = threadIdx.x;
    const int wid = tid >> 5, lane = tid & 31;
    const int g = lane >> 2, q = lane & 3;
    const int m0 = blockIdx.y * GTM, n0 = blockIdx.x * GTN;
    const int wm = (wid >> 1) * 64, wn = (wid & 1) * 64;

    float acc[4][8][4];
    gemm_mainloop(A, Bm, m0, n0, acc);

#pragma unroll
    for (int mi = 0; mi < 4; mi++) {
        int row = m0 + wm + mi * 16 + g;
        int t0 = row & (SS - 1);
        int t1 = (row + 8) & (SS - 1);
#pragma unroll
        for (int ni = 0; ni < 8; ni++) {
            int col = n0 + wn + ni * 8 + q * 2;
            float e0 = acc[mi][ni][0], o0 = acc[mi][ni][1];
            float e1 = acc[mi][ni][2], o1 = acc[mi][ni][3];
            if (z < 2) {
                int i = (col & 127) >> 1;
                float c0 = fc[t0 * 64 + i], s0 = fs[t0 * 64 + i];
                float c1 = fc[t1 * 64 + i], s1 = fs[t1 * 64 + i];
                float re0 = e0 * c0 - o0 * s0, ro0 = e0 * s0 + o0 * c0;
                float re1 = e1 * c1 - o1 * s1, ro1 = e1 * s1 + o1 * c1;
                e0 = re0; o0 = ro0; e1 = re1; o1 = ro1;
            }
            *(__half2*)(C + (size_t)row * DD + col) = __floats2half2_rn(e0, o0);
            *(__half2*)(C + (size_t)(row + 8) * DD + col) = __floats2half2_rn(e1, o1);
        }
    }
}

// ---------------------------------------------------------------------------
// Single conversion pass: x + 4 weights -> half
// ---------------------------------------------------------------------------
#define N4X (MDIM * KDIM / 4)      // 2097152
#define N4W (NDIM * KDIM / 4)      // 1048576
__global__ void cvt_all_kernel(const float* __restrict__ x,
                               const float* __restrict__ wq,
                               const float* __restrict__ wk,
                               const float* __restrict__ wv,
                               const float* __restrict__ wo)
{
    int idx = blockIdx.x * blockDim.x + threadIdx.x;
    const float* src;
    __half* dst;
    int off;
    if (idx < N4X) { src = x; dst = g_xh; off = idx; }
    else {
        int j = idx - N4X;
        int w = j >> 20;
        off = j & (N4W - 1);
        if (w == 0)      { src = wq; dst = g_wqh; }
        else if (w == 1) { src = wk; dst = g_wkh; }
        else if (w == 2) { src = wv; dst = g_wvh; }
        else             { src = wo; dst = g_woh; }
    }
    float4 v = ((const float4*)src)[off];
    __half2 h0 = __floats2half2_rn(v.x, v.y);
    __half2 h1 = __floats2half2_rn(v.z, v.w);
    uint2 u;
    u.x = *(uint32_t*)&h0;
    u.y = *(uint32_t*)&h1;
    ((uint2*)dst)[off] = u;
}

// ---------------------------------------------------------------------------
// Flash attention, fp16 mma + ldmatrix, causal — EXACT R14 version
// (256 threads, FBQ=128, 1 CTA/SM, known good).
// ---------------------------------------------------------------------------
#define FBQ 128
#define FBK 64
#define FSCALE 0.08838834764831845f
#define KVSTR 272
#define KOFF0 0
#define VOFF0 17408
#define KOFF1 34816
#define VOFF1 52224
#define PSOFF 69632
#define PSTR 144
#define FLASH_SMEM (PSOFF + FBQ * PSTR)    // 88064 B

__device__ __forceinline__ void flash_load_kv(uint32_t sb, int buf, int k0,
                                              size_t brow, size_t head, int tid)
{
    const uint32_t kb = sb + (buf ? KOFF1 : KOFF0);
    const uint32_t vb = sb + (buf ? VOFF1 : VOFF0);
#pragma unroll
    for (int i = 0; i < 4; i++) {
        int id = tid + i * 256;
        int r = id >> 4, c = id & 15;
        cp_async16(kb + r * KVSTR + c * 16, g_Kh + (brow + k0 + r) * (size_t)DD + head + c * 8);
        cp_async16(vb + r * KVSTR + c * 16, g_Vh + (brow + k0 + r) * (size_t)DD + head + c * 8);
    }
}

__global__ void __launch_bounds__(256, 1) flash_f16_kernel()
{
    extern __shared__ __align__(16) char smem[];
    const uint32_t sb = smem_u32(smem);
    const int tid = threadIdx.x;
    const int wid = tid >> 5, lane = tid & 31;
    const int g = lane >> 2, q = lane & 3;
    const int l15 = lane & 15, lhi = (lane >> 4) * 16;
    const int q0 = (gridDim.x - 1 - blockIdx.x) * FBQ;
    const int h = blockIdx.y, b = blockIdx.z;
    const size_t brow = (size_t)b * SS;
    const size_t head = (size_t)h * FHD;

#pragma unroll
    for (int i = 0; i < 8; i++) {
        int id = tid + i * 256;
        int r = id >> 4, c = id & 15;
        cp_async16(sb + r * KVSTR + c * 16, g_Qh + (brow + q0 + r) * (size_t)DD + head + c * 8);
    }
    cp_commit(); cp_wait<0>(); __syncthreads();

    uint32_t qf[8][4];
#pragma unroll
    for (int ks = 0; ks < 8; ks++)
        ldsm4(qf[ks][0], qf[ks][1], qf[ks][2], qf[ks][3],
              sb + (wid * 16 + l15) * KVSTR + ks * 32 + lhi);
    __syncthreads();

    const int rl0 = wid * 16 + g, rl1 = rl0 + 8;
    const int rg0 = q0 + rl0, rg1 = rg0 + 8;

    float m0 = -1e30f, m1 = -1e30f, l0 = 0.0f, l1 = 0.0f;
    float o[16][4];
#pragma unroll
    for (int nf = 0; nf < 16; nf++)
#pragma unroll
        for (int j = 0; j < 4; j++) o[nf][j] = 0.0f;

    const int ktiles = q0 / FBK + 2;
    flash_load_kv(sb, 0, 0, brow, head, tid);
    cp_commit();

    for (int t = 0; t < ktiles; t++) {
        if (t + 1 < ktiles)
            flash_load_kv(sb, (t + 1) & 1, (t + 1) * FBK, brow, head, tid);
        cp_commit();
        cp_wait<1>();
        __syncthreads();

        const int k0 = t * FBK;
        const uint32_t kb = sb + ((t & 1) ? KOFF1 : KOFF0);
        const uint32_t vb = sb + ((t & 1) ? VOFF1 : VOFF0);

        float s[8][4];
#pragma unroll
        for (int nf = 0; nf < 8; nf++)
#pragma unroll
            for (int j = 0; j < 4; j++) s[nf][j] = 0.0f;

#pragma unroll
        for (int ks = 0; ks < 8; ks++) {
#pragma unroll
            for (int nj = 0; nj < 4; nj++) {
                uint32_t b0, b1, b2, b3;
                ldsm4(b0, b1, b2, b3, kb + (nj * 16 + l15) * KVSTR + ks * 32 + lhi);
                mma_f16(s[2 * nj],     qf[ks], b0, b2);
                mma_f16(s[2 * nj + 1], qf[ks], b1, b3);
            }
        }

#pragma unroll
        for (int nf = 0; nf < 8; nf++)
#pragma unroll
            for (int j = 0; j < 4; j++) s[nf][j] *= FSCALE;

        if (k0 + FBK - 1 > q0 + wid * 16) {
#pragma unroll
            for (int nf = 0; nf < 8; nf++) {
                int c0 = k0 + nf * 8 + 2 * q;
                if (c0 > rg0)     s[nf][0] = -1e30f;
                if (c0 + 1 > rg0) s[nf][1] = -1e30f;
                if (c0 > rg1)     s[nf][2] = -1e30f;
                if (c0 + 1 > rg1) s[nf][3] = -1e30f;
            }
        }

        float mx0 = -1e30f, mx1 = -1e30f;
#pragma unroll
        for (int nf = 0; nf < 8; nf++) {
            mx0 = fmaxf(mx0, fmaxf(s[nf][0], s[nf][1]));
            mx1 = fmaxf(mx1, fmaxf(s[nf][2], s[nf][3]));
        }
        mx0 = fmaxf(mx0, __shfl_xor_sync(0xffffffffu, mx0, 1));
        mx0 = fmaxf(mx0, __shfl_xor_sync(0xffffffffu, mx0, 2));
        mx1 = fmaxf(mx1, __shfl_xor_sync(0xffffffffu, mx1, 1));
        mx1 = fmaxf(mx1, __shfl_xor_sync(0xffffffffu, mx1, 2));

        float mn0 = fmaxf(m0, mx0), mn1 = fmaxf(m1, mx1);
        float cr0 = __expf(m0 - mn0), cr1 = __expf(m1 - mn1);
        m0 = mn0; m1 = mn1;

        float rs0 = 0.0f, rs1 = 0.0f;
#pragma unroll
        for (int nf = 0; nf < 8; nf++) {
            s[nf][0] = __expf(s[nf][0] - mn0);
            s[nf][1] = __expf(s[nf][1] - mn0);
            s[nf][2] = __expf(s[nf][2] - mn1);
            s[nf][3] = __expf(s[nf][3] - mn1);
            rs0 += s[nf][0] + s[nf][1];
            rs1 += s[nf][2] + s[nf][3];
        }
        rs0 += __shfl_xor_sync(0xffffffffu, rs0, 1);
        rs0 += __shfl_xor_sync(0xffffffffu, rs0, 2);
        rs1 += __shfl_xor_sync(0xffffffffu, rs1, 1);
        rs1 += __shfl_xor_sync(0xffffffffu, rs1, 2);
        l0 = l0 * cr0 + rs0;
        l1 = l1 * cr1 + rs1;

#pragma unroll
        for (int nf = 0; nf < 16; nf++) {
            o[nf][0] *= cr0; o[nf][1] *= cr0;
            o[nf][2] *= cr1; o[nf][3] *= cr1;
        }

#pragma unroll
        for (int nf = 0; nf < 8; nf++) {
            *(__half2*)(smem + PSOFF + rl0 * PSTR + (nf * 8 + 2 * q) * 2) =
                __floats2half2_rn(s[nf][0], s[nf][1]);
            *(__half2*)(smem + PSOFF + rl1 * PSTR + (nf * 8 + 2 * q) * 2) =
                __floats2half2_rn(s[nf][2], s[nf][3]);
        }
        __syncwarp();

#pragma unroll
        for (int ks2 = 0; ks2 < 4; ks2++) {
            uint32_t pa[4];
            ldsm4(pa[0], pa[1], pa[2], pa[3],
                  sb + PSOFF + (wid * 16 + l15) * PSTR + ks2 * 32 + lhi);
#pragma unroll
            for (int nj = 0; nj < 8; nj++) {
                uint32_t v0, v1, v2, v3;
                ldsm4t(v0, v1, v2, v3,
                       vb + (ks2 * 16 + l15) * KVSTR + nj * 32 + lhi);
                mma_f16(o[2 * nj],     pa, v0, v1);
                mma_f16(o[2 * nj + 1], pa, v2, v3);
            }
        }
        __syncthreads();
    }

    float i0 = 1.0f / l0, i1 = 1.0f / l1;
#pragma unroll
    for (int nf = 0; nf < 16; nf++) {
        *(__half2*)(g_AOh + (brow + rg0) * (size_t)DD + head + nf * 8 + 2 * q) =
            __floats2half2_rn(o[nf][0] * i0, o[nf][1] * i0);
        *(__half2*)(g_AOh + (brow + rg1) * (size_t)DD + head + nf * 8 + 2 * q) =
            __floats2half2_rn(o[nf][2] * i1, o[nf][3] * i1);
    }
}

// ---------------------------------------------------------------------------
// Launch
// ---------------------------------------------------------------------------
extern "C" void kernel_launch(void* const* d_in, const int* in_sizes, int n_in,
                              void* d_out, int out_size)
{
    const float* x  = (const float*)d_in[0];
    const float* wq = (const float*)d_in[1];
    const float* wk = (const float*)d_in[2];
    const float* wv = (const float*)d_in[3];
    const float* wo = (const float*)d_in[4];
    const float* fc = (const float*)d_in[5];
    const float* fs = (const float*)d_in[6];
    float* out = (float*)d_out;

    void *p_xh, *p_woh, *p_aoh;
    cudaGetSymbolAddress(&p_xh,  g_xh);
    cudaGetSymbolAddress(&p_woh, g_woh);
    cudaGetSymbolAddress(&p_aoh, g_AOh);

    cudaFuncSetAttribute(gemm_f16_kernel,
                         cudaFuncAttributeMaxDynamicSharedMemorySize, GEMM_SMEM);
    cudaFuncSetAttribute(qkv_f16_kernel,
                         cudaFuncAttributeMaxDynamicSharedMemorySize, GEMM_SMEM);
    cudaFuncSetAttribute(flash_f16_kernel,
                         cudaFuncAttributeMaxDynamicSharedMemorySize, FLASH_SMEM);

    // 0) one conversion pass: x + 4 weights -> half
    cvt_all_kernel<<<(N4X + 4 * N4W) / 256, 256>>>(x, wq, wk, wv, wo);

    // 1) QKV projections with fused RoPE epilogue -> g_Qh/g_Kh/g_Vh (half)
    dim3 gq(NDIM / GTN, MDIM / GTM, 3);   // (16, 32, 3)
    qkv_f16_kernel<<<gq, NTHR, GEMM_SMEM>>>((const __half*)p_xh, fc, fs);

    // 2) Causal flash attention -> g_AOh  (R14 shape: 128-row q tiles)
    flash_f16_kernel<<<dim3(SS / FBQ, NH, BB), 256, FLASH_SMEM>>>();

    // 3) Output projection -> fp32 out
    gemm_f16_kernel<<<dim3(NDIM / GTN, MDIM / GTM), NTHR, GEMM_SMEM>>>(
        (const __half*)p_aoh, (const __half*)p_woh, out);
}

// round 17
// speedup vs baseline: 1.0235x; 1.0235x over previous
#include <cuda_runtime.h>
#include <cuda_fp16.h>
#include <cstddef>
#include <cstdint>

// Problem constants
#define BB 2
#define SS 2048
#define DD 2048
#define NH 16
#define FHD 128
#define KDIM 2048
#define NDIM 2048
#define MDIM (BB * SS)   // 4096

// ---------------------------------------------------------------------------
// Scratch (device globals — no allocation allowed)
// ---------------------------------------------------------------------------
__device__ __half g_Qh[(size_t)MDIM * DD];
__device__ __half g_Kh[(size_t)MDIM * DD];
__device__ __half g_Vh[(size_t)MDIM * DD];
__device__ __half g_AOh[(size_t)MDIM * DD];
__device__ __half g_xh[(size_t)MDIM * KDIM];
__device__ __half g_wqh[(size_t)NDIM * KDIM];
__device__ __half g_wkh[(size_t)NDIM * KDIM];
__device__ __half g_wvh[(size_t)NDIM * KDIM];
__device__ __half g_woh[(size_t)NDIM * KDIM];

// ---------------------------------------------------------------------------
// Helpers
// ---------------------------------------------------------------------------
__device__ __forceinline__ uint32_t smem_u32(const void* p) {
    uint32_t a;
    asm("{ .reg .u64 t; cvta.to.shared.u64 t, %1; cvt.u32.u64 %0, t; }" : "=r"(a) : "l"(p));
    return a;
}
__device__ __forceinline__ void cp_async16(uint32_t dst, const void* src) {
    asm volatile("cp.async.cg.shared.global [%0], [%1], 16;" :: "r"(dst), "l"(src) : "memory");
}
__device__ __forceinline__ void cp_commit() {
    asm volatile("cp.async.commit_group;" ::: "memory");
}
template <int N>
__device__ __forceinline__ void cp_wait() {
    asm volatile("cp.async.wait_group %0;" :: "n"(N) : "memory");
}
__device__ __forceinline__ void ldsm4(uint32_t& r0, uint32_t& r1, uint32_t& r2, uint32_t& r3,
                                      uint32_t addr) {
    asm volatile("ldmatrix.sync.aligned.m8n8.x4.shared.b16 {%0,%1,%2,%3}, [%4];"
                 : "=r"(r0), "=r"(r1), "=r"(r2), "=r"(r3) : "r"(addr));
}
__device__ __forceinline__ void ldsm4t(uint32_t& r0, uint32_t& r1, uint32_t& r2, uint32_t& r3,
                                       uint32_t addr) {
    asm volatile("ldmatrix.sync.aligned.m8n8.x4.trans.shared.b16 {%0,%1,%2,%3}, [%4];"
                 : "=r"(r0), "=r"(r1), "=r"(r2), "=r"(r3) : "r"(addr));
}
__device__ __forceinline__ void mma_f16(float* d, const uint32_t* a, uint32_t b0, uint32_t b1)
{
    asm volatile(
        "mma.sync.aligned.m16n8k16.row.col.f32.f16.f16.f32 "
        "{%0,%1,%2,%3}, {%4,%5,%6,%7}, {%8,%9}, {%0,%1,%2,%3};"
        : "+f"(d[0]), "+f"(d[1]), "+f"(d[2]), "+f"(d[3])
        : "r"(a[0]), "r"(a[1]), "r"(a[2]), "r"(a[3]), "r"(b0), "r"(b1));
}

// ---------------------------------------------------------------------------
// fp16 mma GEMM mainloop (exact R14): 128-thread CTA, 4 warps of 64x64,
// 2 CTAs/SM, K-tile 32, 4-stage ring, one barrier per k-tile,
// double-buffered ldmatrix fragments.
// ---------------------------------------------------------------------------
#define GTM 128
#define GTN 128
#define GTK 32
#define GSTR 80
#define NTHR 128
#define A_T_B (GTM * GSTR)                 // 10240
#define B_T_B (GTN * GSTR)                 // 10240
#define STG_B (A_T_B + B_T_B)              // 20480
#define NSTG 4
#define GEMM_SMEM (NSTG * STG_B)           // 81920 (x2 CTAs = 163.8 KB/SM)
#define KT (KDIM / GTK)                    // 64

__device__ __forceinline__ void gemm_load_stage(uint32_t sbase, int s, int kt,
                                                const __half* __restrict__ A,
                                                const __half* __restrict__ Bm,
                                                int m0, int n0, int tid)
{
    const uint32_t ab = sbase + s * STG_B;
    const uint32_t bb = ab + A_T_B;
    const int kk = kt * GTK;
#pragma unroll
    for (int i = 0; i < 4; i++) {
        int t = tid + i * NTHR;
        int r = t >> 2, c = t & 3;
        cp_async16(ab + r * GSTR + c * 16, A + (size_t)(m0 + r) * KDIM + kk + c * 8);
    }
#pragma unroll
    for (int i = 0; i < 4; i++) {
        int t = tid + i * NTHR;
        int r = t >> 2, c = t & 3;
        cp_async16(bb + r * GSTR + c * 16, Bm + (size_t)(n0 + r) * KDIM + kk + c * 8);
    }
}

__device__ __forceinline__ void gemm_mainloop(const __half* __restrict__ A,
                                              const __half* __restrict__ Bm,
                                              int m0, int n0,
                                              float acc[4][8][4])
{
    extern __shared__ __align__(16) char smem[];
    const uint32_t sbase = smem_u32(smem);
    const int tid = threadIdx.x;
    const int wid = tid >> 5, lane = tid & 31;
    const int wm = (wid >> 1) * 64, wn = (wid & 1) * 64;
    const int l15 = lane & 15, lhi = (lane >> 4) * 16;
    const uint32_t aoff = (wm + l15) * GSTR + lhi;
    const uint32_t boff = (wn + l15) * GSTR + lhi;

#pragma unroll
    for (int mi = 0; mi < 4; mi++)
#pragma unroll
        for (int ni = 0; ni < 8; ni++)
#pragma unroll
            for (int j = 0; j < 4; j++) acc[mi][ni][j] = 0.0f;

#pragma unroll
    for (int s = 0; s < NSTG - 1; s++) {
        gemm_load_stage(sbase, s, s, A, Bm, m0, n0, tid);
        cp_commit();
    }
    cp_wait<2>();
    __syncthreads();

    uint32_t a0[4][4], b0f[4][4];
    uint32_t a1[4][4], b1f[4][4];
    {
        const uint32_t ab = sbase;
        const uint32_t bb = ab + A_T_B;
#pragma unroll
        for (int mi = 0; mi < 4; mi++)
            ldsm4(a0[mi][0], a0[mi][1], a0[mi][2], a0[mi][3],
                  ab + aoff + mi * 16 * GSTR);
#pragma unroll
        for (int nj = 0; nj < 4; nj++)
            ldsm4(b0f[nj][0], b0f[nj][1], b0f[nj][2], b0f[nj][3],
                  bb + boff + nj * 16 * GSTR);
    }

    int st_cur = 0, st_wr = NSTG - 1;
    for (int kt = 0; kt < KT; kt++) {
        cp_wait<2>();
        __syncthreads();
        if (kt + NSTG - 1 < KT)
            gemm_load_stage(sbase, st_wr, kt + NSTG - 1, A, Bm, m0, n0, tid);
        cp_commit();

        const uint32_t ab = sbase + st_cur * STG_B;
        const uint32_t bb = ab + A_T_B;
        const int st_nxt = (st_cur + 1 == NSTG) ? 0 : st_cur + 1;

#pragma unroll
        for (int mi = 0; mi < 4; mi++)
            ldsm4(a1[mi][0], a1[mi][1], a1[mi][2], a1[mi][3],
                  ab + aoff + mi * 16 * GSTR + 32);
#pragma unroll
        for (int nj = 0; nj < 4; nj++)
            ldsm4(b1f[nj][0], b1f[nj][1], b1f[nj][2], b1f[nj][3],
                  bb + boff + nj * 16 * GSTR + 32);

#pragma unroll
        for (int nj = 0; nj < 4; nj++)
#pragma unroll
            for (int mi = 0; mi < 4; mi++) {
                mma_f16(acc[mi][2 * nj],     a0[mi], b0f[nj][0], b0f[nj][2]);
                mma_f16(acc[mi][2 * nj + 1], a0[mi], b0f[nj][1], b0f[nj][3]);
            }

        if (kt + 1 < KT) {
            const uint32_t abn = sbase + st_nxt * STG_B;
            const uint32_t bbn = abn + A_T_B;
#pragma unroll
            for (int mi = 0; mi < 4; mi++)
                ldsm4(a0[mi][0], a0[mi][1], a0[mi][2], a0[mi][3],
                      abn + aoff + mi * 16 * GSTR);
#pragma unroll
            for (int nj = 0; nj < 4; nj++)
                ldsm4(b0f[nj][0], b0f[nj][1], b0f[nj][2], b0f[nj][3],
                      bbn + boff + nj * 16 * GSTR);
        }

#pragma unroll
        for (int nj = 0; nj < 4; nj++)
#pragma unroll
            for (int mi = 0; mi < 4; mi++) {
                mma_f16(acc[mi][2 * nj],     a1[mi], b1f[nj][0], b1f[nj][2]);
                mma_f16(acc[mi][2 * nj + 1], a1[mi], b1f[nj][1], b1f[nj][3]);
            }

        st_cur = st_nxt;
        st_wr = (st_wr + 1 == NSTG) ? 0 : st_wr + 1;
    }
}

__global__ void __launch_bounds__(NTHR, 2) gemm_f16_kernel(
    const __half* __restrict__ A, const __half* __restrict__ Bm, float* __restrict__ C)
{
    const int tid = threadIdx.x;
    const int wid = tid >> 5, lane = tid & 31;
    const int g = lane >> 2, q = lane & 3;
    const int m0 = blockIdx.y * GTM, n0 = blockIdx.x * GTN;
    const int wm = (wid >> 1) * 64, wn = (wid & 1) * 64;

    float acc[4][8][4];
    gemm_mainloop(A, Bm, m0, n0, acc);

#pragma unroll
    for (int mi = 0; mi < 4; mi++) {
        int row = m0 + wm + mi * 16 + g;
#pragma unroll
        for (int ni = 0; ni < 8; ni++) {
            int col = n0 + wn + ni * 8 + q * 2;
            *(float2*)(C + (size_t)row * NDIM + col) =
                make_float2(acc[mi][ni][0], acc[mi][ni][1]);
            *(float2*)(C + (size_t)(row + 8) * NDIM + col) =
                make_float2(acc[mi][ni][2], acc[mi][ni][3]);
        }
    }
}

__global__ void __launch_bounds__(NTHR, 2) qkv_f16_kernel(
    const __half* __restrict__ A,
    const float* __restrict__ fc, const float* __restrict__ fs)
{
    const __half* Bm;
    __half* C;
    const int z = blockIdx.z;
    if (z == 0)      { Bm = g_wqh; C = g_Qh; }
    else if (z == 1) { Bm = g_wkh; C = g_Kh; }
    else             { Bm = g_wvh; C = g_Vh; }

    const int tid = threadIdx.x;
    const int wid = tid >> 5, lane = tid & 31;
    const int g = lane >> 2, q = lane & 3;
    const int m0 = blockIdx.y * GTM, n0 = blockIdx.x * GTN;
    const int wm = (wid >> 1) * 64, wn = (wid & 1) * 64;

    float acc[4][8][4];
    gemm_mainloop(A, Bm, m0, n0, acc);

#pragma unroll
    for (int mi = 0; mi < 4; mi++) {
        int row = m0 + wm + mi * 16 + g;
        int t0 = row & (SS - 1);
        int t1 = (row + 8) & (SS - 1);
#pragma unroll
        for (int ni = 0; ni < 8; ni++) {
            int col = n0 + wn + ni * 8 + q * 2;
            float e0 = acc[mi][ni][0], o0 = acc[mi][ni][1];
            float e1 = acc[mi][ni][2], o1 = acc[mi][ni][3];
            if (z < 2) {
                int i = (col & 127) >> 1;
                float c0 = fc[t0 * 64 + i], s0 = fs[t0 * 64 + i];
                float c1 = fc[t1 * 64 + i], s1 = fs[t1 * 64 + i];
                float re0 = e0 * c0 - o0 * s0, ro0 = e0 * s0 + o0 * c0;
                float re1 = e1 * c1 - o1 * s1, ro1 = e1 * s1 + o1 * c1;
                e0 = re0; o0 = ro0; e1 = re1; o1 = ro1;
            }
            *(__half2*)(C + (size_t)row * DD + col) = __floats2half2_rn(e0, o0);
            *(__half2*)(C + (size_t)(row + 8) * DD + col) = __floats2half2_rn(e1, o1);
        }
    }
}

// ---------------------------------------------------------------------------
// Single conversion pass: x + 4 weights -> half
// ---------------------------------------------------------------------------
#define N4X (MDIM * KDIM / 4)      // 2097152
#define N4W (NDIM * KDIM / 4)      // 1048576
__global__ void cvt_all_kernel(const float* __restrict__ x,
                               const float* __restrict__ wq,
                               const float* __restrict__ wk,
                               const float* __restrict__ wv,
                               const float* __restrict__ wo)
{
    int idx = blockIdx.x * blockDim.x + threadIdx.x;
    const float* src;
    __half* dst;
    int off;
    if (idx < N4X) { src = x; dst = g_xh; off = idx; }
    else {
        int j = idx - N4X;
        int w = j >> 20;
        off = j & (N4W - 1);
        if (w == 0)      { src = wq; dst = g_wqh; }
        else if (w == 1) { src = wk; dst = g_wkh; }
        else if (w == 2) { src = wv; dst = g_wvh; }
        else             { src = wo; dst = g_woh; }
    }
    float4 v = ((const float4*)src)[off];
    __half2 h0 = __floats2half2_rn(v.x, v.y);
    __half2 h1 = __floats2half2_rn(v.z, v.w);
    uint2 u;
    u.x = *(uint32_t*)&h0;
    u.y = *(uint32_t*)&h1;
    ((uint2*)dst)[off] = u;
}

// ---------------------------------------------------------------------------
// Flash attention: R14 per-warp math, KV TRIPLE-buffered so the bottom
// __syncthreads is removed (prefetch at iter t writes buf (t+1)%3; last read
// of that buffer was iter t-2, separated by the top barrier of iter t-1).
// 256 threads, FBQ=128, 1 CTA/SM.
// ---------------------------------------------------------------------------
#define FBQ 128
#define FBK 64
#define FSCALE 0.08838834764831845f
#define KVSTR 272
#define KVB 34816                      // one K+V buffer (2 x 64 x 272)
#define PSOFF (3 * KVB)                // 104448
#define PSTR 144
#define FLASH_SMEM (PSOFF + FBQ * PSTR)    // 122880 B

__device__ __forceinline__ void flash_load_kv(uint32_t sb, int buf, int k0,
                                              size_t brow, size_t head, int tid)
{
    const uint32_t kb = sb + buf * KVB;
    const uint32_t vb = kb + 17408;
#pragma unroll
    for (int i = 0; i < 4; i++) {
        int id = tid + i * 256;
        int r = id >> 4, c = id & 15;
        cp_async16(kb + r * KVSTR + c * 16, g_Kh + (brow + k0 + r) * (size_t)DD + head + c * 8);
        cp_async16(vb + r * KVSTR + c * 16, g_Vh + (brow + k0 + r) * (size_t)DD + head + c * 8);
    }
}

__global__ void __launch_bounds__(256, 1) flash_f16_kernel()
{
    extern __shared__ __align__(16) char smem[];
    const uint32_t sb = smem_u32(smem);
    const int tid = threadIdx.x;
    const int wid = tid >> 5, lane = tid & 31;
    const int g = lane >> 2, q = lane & 3;
    const int l15 = lane & 15, lhi = (lane >> 4) * 16;
    const int q0 = (gridDim.x - 1 - blockIdx.x) * FBQ;
    const int h = blockIdx.y, b = blockIdx.z;
    const size_t brow = (size_t)b * SS;
    const size_t head = (size_t)h * FHD;

    // Prologue: stage Q tile (128 rows, stride 272) at buffer 0
#pragma unroll
    for (int i = 0; i < 8; i++) {
        int id = tid + i * 256;
        int r = id >> 4, c = id & 15;
        cp_async16(sb + r * KVSTR + c * 16, g_Qh + (brow + q0 + r) * (size_t)DD + head + c * 8);
    }
    cp_commit(); cp_wait<0>(); __syncthreads();

    uint32_t qf[8][4];
#pragma unroll
    for (int ks = 0; ks < 8; ks++)
        ldsm4(qf[ks][0], qf[ks][1], qf[ks][2], qf[ks][3],
              sb + (wid * 16 + l15) * KVSTR + ks * 32 + lhi);
    __syncthreads();   // all warps done reading Q before buf0 is overwritten

    const int rl0 = wid * 16 + g, rl1 = rl0 + 8;
    const int rg0 = q0 + rl0, rg1 = rg0 + 8;

    float m0 = -1e30f, m1 = -1e30f, l0 = 0.0f, l1 = 0.0f;
    float o[16][4];
#pragma unroll
    for (int nf = 0; nf < 16; nf++)
#pragma unroll
        for (int j = 0; j < 4; j++) o[nf][j] = 0.0f;

    const int ktiles = q0 / FBK + 2;
    flash_load_kv(sb, 0, 0, brow, head, tid);
    cp_commit();

    int buf_cur = 0;
    for (int t = 0; t < ktiles; t++) {
        if (t + 1 < ktiles) {
            int bn = buf_cur + 1 == 3 ? 0 : buf_cur + 1;
            flash_load_kv(sb, bn, (t + 1) * FBK, brow, head, tid);
        }
        cp_commit();
        cp_wait<1>();
        __syncthreads();

        const int k0 = t * FBK;
        const uint32_t kb = sb + buf_cur * KVB;
        const uint32_t vb = kb + 17408;

        float s[8][4];
#pragma unroll
        for (int nf = 0; nf < 8; nf++)
#pragma unroll
            for (int j = 0; j < 4; j++) s[nf][j] = 0.0f;

#pragma unroll
        for (int ks = 0; ks < 8; ks++) {
#pragma unroll
            for (int nj = 0; nj < 4; nj++) {
                uint32_t b0, b1, b2, b3;
                ldsm4(b0, b1, b2, b3, kb + (nj * 16 + l15) * KVSTR + ks * 32 + lhi);
                mma_f16(s[2 * nj],     qf[ks], b0, b2);
                mma_f16(s[2 * nj + 1], qf[ks], b1, b3);
            }
        }

#pragma unroll
        for (int nf = 0; nf < 8; nf++)
#pragma unroll
            for (int j = 0; j < 4; j++) s[nf][j] *= FSCALE;

        if (k0 + FBK - 1 > q0 + wid * 16) {
#pragma unroll
            for (int nf = 0; nf < 8; nf++) {
                int c0 = k0 + nf * 8 + 2 * q;
                if (c0 > rg0)     s[nf][0] = -1e30f;
                if (c0 + 1 > rg0) s[nf][1] = -1e30f;
                if (c0 > rg1)     s[nf][2] = -1e30f;
                if (c0 + 1 > rg1) s[nf][3] = -1e30f;
            }
        }

        float mx0 = -1e30f, mx1 = -1e30f;
#pragma unroll
        for (int nf = 0; nf < 8; nf++) {
            mx0 = fmaxf(mx0, fmaxf(s[nf][0], s[nf][1]));
            mx1 = fmaxf(mx1, fmaxf(s[nf][2], s[nf][3]));
        }
        mx0 = fmaxf(mx0, __shfl_xor_sync(0xffffffffu, mx0, 1));
        mx0 = fmaxf(mx0, __shfl_xor_sync(0xffffffffu, mx0, 2));
        mx1 = fmaxf(mx1, __shfl_xor_sync(0xffffffffu, mx1, 1));
        mx1 = fmaxf(mx1, __shfl_xor_sync(0xffffffffu, mx1, 2));

        float mn0 = fmaxf(m0, mx0), mn1 = fmaxf(m1, mx1);
        float cr0 = __expf(m0 - mn0), cr1 = __expf(m1 - mn1);
        m0 = mn0; m1 = mn1;

        float rs0 = 0.0f, rs1 = 0.0f;
#pragma unroll
        for (int nf = 0; nf < 8; nf++) {
            s[nf][0] = __expf(s[nf][0] - mn0);
            s[nf][1] = __expf(s[nf][1] - mn0);
            s[nf][2] = __expf(s[nf][2] - mn1);
            s[nf][3] = __expf(s[nf][3] - mn1);
            rs0 += s[nf][0] + s[nf][1];
            rs1 += s[nf][2] + s[nf][3];
        }
        rs0 += __shfl_xor_sync(0xffffffffu, rs0, 1);
        rs0 += __shfl_xor_sync(0xffffffffu, rs0, 2);
        rs1 += __shfl_xor_sync(0xffffffffu, rs1, 1);
        rs1 += __shfl_xor_sync(0xffffffffu, rs1, 2);
        l0 = l0 * cr0 + rs0;
        l1 = l1 * cr1 + rs1;

#pragma unroll
        for (int nf = 0; nf < 16; nf++) {
            o[nf][0] *= cr0; o[nf][1] *= cr0;
            o[nf][2] *= cr1; o[nf][3] *= cr1;
        }

        // P write/read is warp-private (rows wid*16..wid*16+15) — syncwarp only
#pragma unroll
        for (int nf = 0; nf < 8; nf++) {
            *(__half2*)(smem + PSOFF + rl0 * PSTR + (nf * 8 + 2 * q) * 2) =
                __floats2half2_rn(s[nf][0], s[nf][1]);
            *(__half2*)(smem + PSOFF + rl1 * PSTR + (nf * 8 + 2 * q) * 2) =
                __floats2half2_rn(s[nf][2], s[nf][3]);
        }
        __syncwarp();

#pragma unroll
        for (int ks2 = 0; ks2 < 4; ks2++) {
            uint32_t pa[4];
            ldsm4(pa[0], pa[1], pa[2], pa[3],
                  sb + PSOFF + (wid * 16 + l15) * PSTR + ks2 * 32 + lhi);
#pragma unroll
            for (int nj = 0; nj < 8; nj++) {
                uint32_t v0, v1, v2, v3;
                ldsm4t(v0, v1, v2, v3,
                       vb + (ks2 * 16 + l15) * KVSTR + nj * 32 + lhi);
                mma_f16(o[2 * nj],     pa, v0, v1);
                mma_f16(o[2 * nj + 1], pa, v2, v3);
            }
        }
        // no bottom __syncthreads: triple-buffering makes the next prefetch safe

        buf_cur = buf_cur + 1 == 3 ? 0 : buf_cur + 1;
    }

    float i0 = 1.0f / l0, i1 = 1.0f / l1;
#pragma unroll
    for (int nf = 0; nf < 16; nf++) {
        *(__half2*)(g_AOh + (brow + rg0) * (size_t)DD + head + nf * 8 + 2 * q) =
            __floats2half2_rn(o[nf][0] * i0, o[nf][1] * i0);
        *(__half2*)(g_AOh + (brow + rg1) * (size_t)DD + head + nf * 8 + 2 * q) =
            __floats2half2_rn(o[nf][2] * i1, o[nf][3] * i1);
    }
}

// ---------------------------------------------------------------------------
// Launch
// ---------------------------------------------------------------------------
extern "C" void kernel_launch(void* const* d_in, const int* in_sizes, int n_in,
                              void* d_out, int out_size)
{
    const float* x  = (const float*)d_in[0];
    const float* wq = (const float*)d_in[1];
    const float* wk = (const float*)d_in[2];
    const float* wv = (const float*)d_in[3];
    const float* wo = (const float*)d_in[4];
    const float* fc = (const float*)d_in[5];
    const float* fs = (const float*)d_in[6];
    float* out = (float*)d_out;

    void *p_xh, *p_woh, *p_aoh;
    cudaGetSymbolAddress(&p_xh,  g_xh);
    cudaGetSymbolAddress(&p_woh, g_woh);
    cudaGetSymbolAddress(&p_aoh, g_AOh);

    cudaFuncSetAttribute(gemm_f16_kernel,
                         cudaFuncAttributeMaxDynamicSharedMemorySize, GEMM_SMEM);
    cudaFuncSetAttribute(qkv_f16_kernel,
                         cudaFuncAttributeMaxDynamicSharedMemorySize, GEMM_SMEM);
    cudaFuncSetAttribute(flash_f16_kernel,
                         cudaFuncAttributeMaxDynamicSharedMemorySize, FLASH_SMEM);

    // 0) one conversion pass: x + 4 weights -> half
    cvt_all_kernel<<<(N4X + 4 * N4W) / 256, 256>>>(x, wq, wk, wv, wo);

    // 1) QKV projections with fused RoPE epilogue -> g_Qh/g_Kh/g_Vh (half)
    dim3 gq(NDIM / GTN, MDIM / GTM, 3);   // (16, 32, 3)
    qkv_f16_kernel<<<gq, NTHR, GEMM_SMEM>>>((const __half*)p_xh, fc, fs);

    // 2) Causal flash attention -> g_AOh
    flash_f16_kernel<<<dim3(SS / FBQ, NH, BB), 256, FLASH_SMEM>>>();

    // 3) Output projection -> fp32 out
    gemm_f16_kernel<<<dim3(NDIM / GTN, MDIM / GTM), NTHR, GEMM_SMEM>>>(
        (const __half*)p_aoh, (const __half*)p_woh, out);
}